// round 8
// baseline (speedup 1.0000x reference)
#include <cuda_runtime.h>
#include <math.h>

#define BN 16
#define DD 512
#define TT 2048
#define CC 20
#define KK 7
#define FF (CC*KK)            // 140
#define PT 2048
#define TS 32                 // similarity tile
#define DKC 32                // k-chunk
#define EPSV 1e-8f
#define BIGV 1e9f
#define THSIM 0.5f
#define THDIF 0.1f
#define SIM_BLOCKS 1184

// -------- scratch (static device globals; no runtime allocation) --------
__device__ float    g_Et[(size_t)BN*DD*PT];   // transposed gathered points [b][d][p]
__device__ int      g_fg_idx[BN*FF];
__device__ int      g_slotmap[BN*TT];
__device__ int      g_sw[BN*PT];
__device__ unsigned char g_sfg[BN*PT];
__device__ unsigned char g_sbg[BN*PT];
__device__ int      g_Nb[BN];
__device__ int      g_bgcnt[BN];
__device__ int      g_sumw[BN];
__device__ int      g_tiles[BN];
__device__ unsigned g_minff[BN*PT];
__device__ unsigned g_maxfb[BN*PT];
__device__ unsigned g_minbb[BN*PT];
__device__ unsigned g_maxbf[BN*PT];
__device__ float    g_perbatch[BN];
__device__ int      g_ticket;

__device__ __forceinline__ unsigned fenc(float f) {
    unsigned u = __float_as_uint(f);
    return (u & 0x80000000u) ? ~u : (u | 0x80000000u);
}
__device__ __forceinline__ float fdec(unsigned x) {
    return (x & 0x80000000u) ? __uint_as_float(x ^ 0x80000000u) : __uint_as_float(~x);
}

#define PACK2(out, lo, hi) asm("mov.b64 %0, {%1, %2};" : "=l"(out) : "f"(lo), "f"(hi))
#define UNPACK2(lo, hi, in) asm("mov.b64 {%0, %1}, %2;" : "=f"(lo), "=f"(hi) : "l"(in))
#define FMA2(d, a, b, c) asm("fma.rn.f32x2 %0, %1, %2, %3;" : "=l"(d) : "l"(a), "l"(b), "l"(c))

// -------- single-pass top-7: per-thread sorted list + tournament merge --------
__global__ void k_topk(const float* __restrict__ cas) {
    int c = blockIdx.x, b = blockIdx.y, tid = threadIdx.x;
    const float* row = cas + ((size_t)b * CC + c) * TT;

    float lv[KK]; int li[KK];
#pragma unroll
    for (int j = 0; j < KK; j++) { lv[j] = -INFINITY; li[j] = 0x7fffffff; }
#pragma unroll
    for (int i = 0; i < 8; i++) {
        int t = tid + i * 256;
        float cv = row[t]; int ci = t;
#pragma unroll
        for (int j = 0; j < KK; j++) {
            bool better = (cv > lv[j]) || (cv == lv[j] && ci < li[j]);
            if (better) { float tv = lv[j]; int ti = li[j]; lv[j] = cv; li[j] = ci; cv = tv; ci = ti; }
        }
    }

    __shared__ float sv[256][KK];
    __shared__ int   si[256][KK];
#pragma unroll
    for (int j = 0; j < KK; j++) { sv[tid][j] = lv[j]; si[tid][j] = li[j]; }

    for (int s = 128; s > 0; s >>= 1) {
        __syncthreads();
        if (tid < s) {
            float mv[KK]; int mi[KK];
            int ia = 0, ib = 0;
#pragma unroll
            for (int j = 0; j < KK; j++) {
                float va = sv[tid][ia],     vb = sv[tid + s][ib];
                int   xa = si[tid][ia],     xb = si[tid + s][ib];
                bool takeA = (va > vb) || (va == vb && xa < xb);
                if (takeA) { mv[j] = va; mi[j] = xa; ia++; }
                else       { mv[j] = vb; mi[j] = xb; ib++; }
            }
#pragma unroll
            for (int j = 0; j < KK; j++) { sv[tid][j] = mv[j]; si[tid][j] = mi[j]; }
        }
    }
    __syncthreads();
    if (tid < KK) g_fg_idx[b * FF + c * KK + tid] = si[0][tid];
}

// -------- prep: unique-point slots, flags, weights, reduction init --------
__global__ void k_prep(const int* __restrict__ click, const int* __restrict__ label,
                       const int* __restrict__ clsnum) {
    int b = blockIdx.x, tid = threadIdx.x;
    int cn = clsnum ? clsnum[0] : CC;
    __shared__ int w[TT];
    __shared__ int woff[8];
    __shared__ int sbase, sbg;
    for (int t = tid; t < TT; t += 256) w[t] = 0;
    unsigned encBig = fenc(BIGV), encNeg = fenc(-BIGV);
    for (int p = tid; p < PT; p += 256) {
        g_minff[b * PT + p] = encBig;
        g_maxfb[b * PT + p] = encNeg;
        g_minbb[b * PT + p] = encBig;
        g_maxbf[b * PT + p] = encNeg;
    }
    if (tid == 0) { sbase = 0; sbg = 0; }
    __syncthreads();
    for (int i = tid; i < FF; i += 256) {
        int c = i / KK;
        if (label[b * CC + c] == 1) atomicAdd(&w[g_fg_idx[b * FF + i]], 1);
    }
    __syncthreads();
    for (int chunk = 0; chunk < TT; chunk += 256) {
        int t = chunk + tid;
        int bg  = (click[b * TT + t] == cn) ? 1 : 0;
        int wt  = w[t];
        int sel = (bg || wt > 0) ? 1 : 0;
        unsigned ball = __ballot_sync(0xffffffffu, sel);
        unsigned ballbg = __ballot_sync(0xffffffffu, bg);
        int wi = tid >> 5, lane = tid & 31;
        if (lane == 0) { woff[wi] = __popc(ball); atomicAdd(&sbg, __popc(ballbg)); }
        __syncthreads();
        if (tid == 0) {
            int s = sbase;
            for (int i = 0; i < 8; i++) { int cc2 = woff[i]; woff[i] = s; s += cc2; }
            sbase = s;
        }
        __syncthreads();
        if (sel) {
            int pos = woff[wi] + __popc(ball & ((1u << lane) - 1u));
            g_slotmap[b * TT + t] = pos;
            g_sw[b * PT + pos] = wt;
            g_sfg[b * PT + pos] = (wt > 0) ? 1 : 0;
            g_sbg[b * PT + pos] = (unsigned char)bg;
        } else {
            g_slotmap[b * TT + t] = -1;
        }
        __syncthreads();
    }
    if (tid == 0) {
        int numpos = 0;
        for (int c = 0; c < CC; c++) numpos += (label[b * CC + c] == 1) ? 1 : 0;
        g_sumw[b]  = KK * numpos;
        g_bgcnt[b] = sbg;
        g_Nb[b]    = sbase;
        g_tiles[b] = (sbase + TS - 1) / TS;
    }
}

// -------- transpose-gather: 4 d-rows/block, 8 loads in flight, shared slotmap --------
__global__ void k_gatherT(const float* __restrict__ emb) {
    int b = blockIdx.y, tid = threadIdx.x;
    int d0 = blockIdx.x * 4;
    __shared__ int smap[TT];
#pragma unroll
    for (int i = 0; i < 8; i++) smap[tid + i * 256] = g_slotmap[b * TT + tid + i * 256];
    __syncthreads();

    const float4* src = (const float4*)(emb + ((size_t)b * DD + d0) * TT);
    float4 v[8];
#pragma unroll
    for (int dd = 0; dd < 4; dd++) {
#pragma unroll
        for (int it = 0; it < 2; it++)
            v[dd * 2 + it] = src[dd * (TT / 4) + tid + it * 256];
    }
    int sA[4], sB[4];
    {
        int t0 = tid * 4, t1 = (tid + 256) * 4;
#pragma unroll
        for (int j = 0; j < 4; j++) { sA[j] = smap[t0 + j]; sB[j] = smap[t1 + j]; }
    }
#pragma unroll
    for (int dd = 0; dd < 4; dd++) {
        float* dst = g_Et + ((size_t)b * DD + d0 + dd) * PT;
        float4 a = v[dd * 2], c = v[dd * 2 + 1];
        if (sA[0] >= 0) dst[sA[0]] = a.x;
        if (sA[1] >= 0) dst[sA[1]] = a.y;
        if (sA[2] >= 0) dst[sA[2]] = a.z;
        if (sA[3] >= 0) dst[sA[3]] = a.w;
        if (sB[0] >= 0) dst[sB[0]] = c.x;
        if (sB[1] >= 0) dst[sB[1]] = c.y;
        if (sB[2] >= 0) dst[sB[2]] = c.z;
        if (sB[3] >= 0) dst[sB[3]] = c.w;
    }
}

// -------- routing: per-row min/max over typed columns, atomic-merged --------
// norms come from smem arrays (computed per-tile in fixed order -> bit-identical everywhere)
__device__ __forceinline__ void route_tile(const float acc[4][4], int b,
                                           int rowb, int colb, int Nb,
                                           int tx, int ty,
                                           const float* __restrict__ nrR,
                                           const float* __restrict__ nrC) {
    float nc[4]; int cfg[4], cbg[4];
#pragma unroll
    for (int j = 0; j < 4; j++) {
        int lc = 4 * tx + j;
        int c = colb + lc;
        bool cok = (c < Nb);
        nc[j]  = nrC[lc];
        cfg[j] = cok && g_sfg[b * PT + c];
        cbg[j] = cok && g_sbg[b * PT + c];
    }
#pragma unroll
    for (int i = 0; i < 4; i++) {
        int lr = 4 * ty + i;
        int ri = rowb + lr;
        float nr = nrR[lr];
        float vFF = BIGV, vBF = -BIGV, vFB = -BIGV, vBB = BIGV;
#pragma unroll
        for (int j = 0; j < 4; j++) {
            float cs = acc[i][j] / fmaxf(nr * nc[j], EPSV);
            if (cfg[j]) { vFF = fminf(vFF, cs); vBF = fmaxf(vBF, cs); }
            if (cbg[j]) { vFB = fmaxf(vFB, cs); vBB = fminf(vBB, cs); }
        }
#pragma unroll
        for (int m = 4; m > 0; m >>= 1) {
            vFF = fminf(vFF, __shfl_xor_sync(0xffffffffu, vFF, m));
            vBF = fmaxf(vBF, __shfl_xor_sync(0xffffffffu, vBF, m));
            vFB = fmaxf(vFB, __shfl_xor_sync(0xffffffffu, vFB, m));
            vBB = fminf(vBB, __shfl_xor_sync(0xffffffffu, vBB, m));
        }
        if (tx == 0 && ri < Nb) {
            if (g_sfg[b * PT + ri]) {
                atomicMin(&g_minff[b * PT + ri], fenc(vFF));
                atomicMax(&g_maxfb[b * PT + ri], fenc(vFB));
            }
            if (g_sbg[b * PT + ri]) {
                atomicMax(&g_maxbf[b * PT + ri], fenc(vBF));
                atomicMin(&g_minbb[b * PT + ri], fenc(vBB));
            }
        }
    }
}

// -------- fused symmetric tiled similarity + on-the-fly norms, f32x2 mainloop --------
__global__ void __launch_bounds__(64) k_sim() {
    __shared__ float As[DKC][TS];
    __shared__ float Bs[DKC][TS];
    __shared__ float sT[TS][TS + 1];
    __shared__ float sqA[8][32];      // [dk-slice][p] sum-of-squares partials (rows)
    __shared__ float sqB[8][32];
    __shared__ float nrmA[TS];
    __shared__ float nrmB[TS];
    __shared__ int   s_off[BN + 1];

    int tid = threadIdx.x;
    int tx = tid & 7, ty = tid >> 3;
    int slice = tid >> 3;             // 0..7 (dk slice for staging)
    int pq = (tid & 7) * 4;           // p-group for staging

    if (tid == 0) {
        int off = 0;
        for (int b = 0; b < BN; b++) { s_off[b] = off; int t = g_tiles[b]; off += t * (t + 1) / 2; }
        s_off[BN] = off;
    }
    __syncthreads();
    int total = s_off[BN];

    for (int item = blockIdx.x; item < total; item += gridDim.x) {
        int b = 0;
        while (b < BN - 1 && item >= s_off[b + 1]) b++;
        int local = item - s_off[b];
        int tiles = g_tiles[b];
        int rt = 0, rem = local;
        while (rem >= tiles - rt) { rem -= tiles - rt; rt++; }
        int ct = rt + rem;
        int Nb = g_Nb[b];
        int rowb = rt * TS, colb = ct * TS;

        unsigned long long acc2[4][2];
#pragma unroll
        for (int i = 0; i < 4; i++) { acc2[i][0] = 0ull; acc2[i][1] = 0ull; }
        float4 sqa = {0.f, 0.f, 0.f, 0.f}, sqb = {0.f, 0.f, 0.f, 0.f};

        const float* Eb = g_Et + (size_t)b * DD * PT;
#pragma unroll 1
        for (int d0 = 0; d0 < DD; d0 += DKC) {
#pragma unroll
            for (int i = 0; i < 4; i++) {
                int dk = i * 8 + slice;
                const float* rsrc = Eb + (size_t)(d0 + dk) * PT;
                float4 r = *(const float4*)(rsrc + rowb + pq);
                float4 c = *(const float4*)(rsrc + colb + pq);
                *(float4*)&As[dk][pq] = r;
                *(float4*)&Bs[dk][pq] = c;
                sqa.x += r.x * r.x; sqa.y += r.y * r.y; sqa.z += r.z * r.z; sqa.w += r.w * r.w;
                sqb.x += c.x * c.x; sqb.y += c.y * c.y; sqb.z += c.z * c.z; sqb.w += c.w * c.w;
            }
            __syncthreads();
#pragma unroll
            for (int dk = 0; dk < DKC; dk++) {
                float4 a = *(const float4*)&As[dk][ty * 4];
                float4 c = *(const float4*)&Bs[dk][tx * 4];
                unsigned long long cp0, cp1, ap;
                PACK2(cp0, c.x, c.y);
                PACK2(cp1, c.z, c.w);
                PACK2(ap, a.x, a.x); FMA2(acc2[0][0], ap, cp0, acc2[0][0]); FMA2(acc2[0][1], ap, cp1, acc2[0][1]);
                PACK2(ap, a.y, a.y); FMA2(acc2[1][0], ap, cp0, acc2[1][0]); FMA2(acc2[1][1], ap, cp1, acc2[1][1]);
                PACK2(ap, a.z, a.z); FMA2(acc2[2][0], ap, cp0, acc2[2][0]); FMA2(acc2[2][1], ap, cp1, acc2[2][1]);
                PACK2(ap, a.w, a.w); FMA2(acc2[3][0], ap, cp0, acc2[3][0]); FMA2(acc2[3][1], ap, cp1, acc2[3][1]);
            }
            __syncthreads();
        }

        // finalize norms (fixed combine order -> identical for a point in every tile)
        *(float4*)&sqA[slice][pq] = sqa;
        *(float4*)&sqB[slice][pq] = sqb;
        __syncthreads();
        if (tid < 32) {
            float s = 0.f;
            const float* col = &sqA[0][tid];
#pragma unroll
            for (int k = 0; k < 8; k++) s += col[k * 32];
            nrmA[tid] = sqrtf(s);
        } else {
            int p = tid - 32;
            float s = 0.f;
            const float* col = &sqB[0][p];
#pragma unroll
            for (int k = 0; k < 8; k++) s += col[k * 32];
            nrmB[p] = sqrtf(s);
        }
        __syncthreads();

        // unpack accumulators
        float acc[4][4];
#pragma unroll
        for (int i = 0; i < 4; i++) {
            UNPACK2(acc[i][0], acc[i][1], acc2[i][0]);
            UNPACK2(acc[i][2], acc[i][3], acc2[i][1]);
        }

        route_tile(acc, b, rowb, colb, Nb, tx, ty, nrmA, nrmB);

        if (rt != ct) {
#pragma unroll
            for (int i = 0; i < 4; i++)
#pragma unroll
                for (int j = 0; j < 4; j++)
                    sT[4 * tx + j][4 * ty + i] = acc[i][j];
            __syncthreads();
            float a2[4][4];
#pragma unroll
            for (int i = 0; i < 4; i++)
#pragma unroll
                for (int j = 0; j < 4; j++)
                    a2[i][j] = sT[4 * ty + i][4 * tx + j];
            __syncthreads();
            route_tile(a2, b, colb, rowb, Nb, tx, ty, nrmB, nrmA);
        }
        __syncthreads();
    }
}

// -------- per-batch weighted means + fused final (last-block ticket) --------
__global__ void k_batch(float* __restrict__ out) {
    int b = blockIdx.x, tid = threadIdx.x;
    int Nb = g_Nb[b];
    float sff = 0.f, sfb = 0.f, sbb = 0.f, sbf = 0.f;
    for (int p = tid; p < Nb; p += 256) {
        if (g_sfg[b * PT + p]) {
            float wv = (float)g_sw[b * PT + p];
            sff += wv * fmaxf(THSIM - fdec(g_minff[b * PT + p]), 0.f);
            sfb += wv * fmaxf(fdec(g_maxfb[b * PT + p]) - THDIF, 0.f);
        }
        if (g_sbg[b * PT + p]) {
            sbb += fmaxf(THSIM - fdec(g_minbb[b * PT + p]), 0.f);
            sbf += fmaxf(fdec(g_maxbf[b * PT + p]) - THDIF, 0.f);
        }
    }
    __shared__ float r1[256], r2[256], r3[256], r4[256];
    __shared__ int s_last;
    r1[tid] = sff; r2[tid] = sfb; r3[tid] = sbb; r4[tid] = sbf;
    __syncthreads();
    for (int s = 128; s > 0; s >>= 1) {
        if (tid < s) {
            r1[tid] += r1[tid + s]; r2[tid] += r2[tid + s];
            r3[tid] += r3[tid + s]; r4[tid] += r4[tid + s];
        }
        __syncthreads();
    }
    if (tid == 0) {
        int cnt = g_bgcnt[b];
        float denf = fmaxf((float)g_sumw[b], 1.f);
        float denb = fmaxf((float)cnt, 1.f);
        float loss = r1[0] / denf + r2[0] / denf + r3[0] / denb + r4[0] / denb;
        g_perbatch[b] = (cnt > 0) ? loss : 0.f;
        __threadfence();
        int old = atomicAdd(&g_ticket, 1);
        s_last = (old == BN - 1) ? 1 : 0;
    }
    __syncthreads();
    if (s_last && tid == 0) {
        volatile float* pb = g_perbatch;
        float s = 0.f; int c = 0;
        for (int bb = 0; bb < BN; bb++) { s += pb[bb]; if (g_bgcnt[bb] > 0) c++; }
        out[0] = s / fmaxf((float)c, 1.f);
        g_ticket = 0;   // reset for next graph replay
    }
}

extern "C" void kernel_launch(void* const* d_in, const int* in_sizes, int n_in,
                              void* d_out, int out_size) {
    const float* emb    = (const float*)d_in[0];
    const float* cas    = (const float*)d_in[1];
    const int*   click  = (const int*)d_in[2];
    const int*   label  = (const int*)d_in[3];
    const int*   clsnum = (n_in >= 5) ? (const int*)d_in[4] : nullptr;

    k_topk   <<<dim3(CC, BN), 256>>>(cas);
    k_prep   <<<BN, 256>>>(click, label, clsnum);
    k_gatherT<<<dim3(DD / 4, BN), 256>>>(emb);
    k_sim    <<<SIM_BLOCKS, 64>>>();
    k_batch  <<<BN, 256>>>((float*)d_out);
}

// round 9
// speedup vs baseline: 1.2568x; 1.2568x over previous
#include <cuda_runtime.h>
#include <math.h>

#define BN 16
#define DD 512
#define TT 2048
#define CC 20
#define KK 7
#define FF (CC*KK)            // 140
#define PT 2048
#define TS 32                 // similarity tile
#define DKC 32                // k-chunk
#define EPSV 1e-8f
#define BIGV 1e9f
#define THSIM 0.5f
#define THDIF 0.1f
#define SIM_BLOCKS 592

// -------- scratch (static device globals; no runtime allocation) --------
__device__ float    g_Et[(size_t)BN*DD*PT];   // transposed gathered points [b][d][p]
__device__ int      g_fg_idx[BN*FF];
__device__ int      g_slotmap[BN*TT];
__device__ int      g_sw[BN*PT];
__device__ unsigned char g_sfg[BN*PT];
__device__ unsigned char g_sbg[BN*PT];
__device__ int      g_Nb[BN];
__device__ int      g_bgcnt[BN];
__device__ int      g_sumw[BN];
__device__ int      g_tiles[BN];
__device__ unsigned g_minff[BN*PT];
__device__ unsigned g_maxfb[BN*PT];
__device__ unsigned g_minbb[BN*PT];
__device__ unsigned g_maxbf[BN*PT];
__device__ float    g_perbatch[BN];
__device__ int      g_ticket;

__device__ __forceinline__ unsigned fenc(float f) {
    unsigned u = __float_as_uint(f);
    return (u & 0x80000000u) ? ~u : (u | 0x80000000u);
}
__device__ __forceinline__ float fdec(unsigned x) {
    return (x & 0x80000000u) ? __uint_as_float(x ^ 0x80000000u) : __uint_as_float(~x);
}

// -------- single-pass top-7: per-thread sorted list + tournament merge --------
__global__ void k_topk(const float* __restrict__ cas) {
    int c = blockIdx.x, b = blockIdx.y, tid = threadIdx.x;
    const float* row = cas + ((size_t)b * CC + c) * TT;

    float lv[KK]; int li[KK];
#pragma unroll
    for (int j = 0; j < KK; j++) { lv[j] = -INFINITY; li[j] = 0x7fffffff; }
#pragma unroll
    for (int i = 0; i < 8; i++) {
        int t = tid + i * 256;
        float cv = row[t]; int ci = t;
#pragma unroll
        for (int j = 0; j < KK; j++) {
            bool better = (cv > lv[j]) || (cv == lv[j] && ci < li[j]);
            if (better) { float tv = lv[j]; int ti = li[j]; lv[j] = cv; li[j] = ci; cv = tv; ci = ti; }
        }
    }

    __shared__ float sv[256][KK];
    __shared__ int   si[256][KK];
#pragma unroll
    for (int j = 0; j < KK; j++) { sv[tid][j] = lv[j]; si[tid][j] = li[j]; }

    for (int s = 128; s > 0; s >>= 1) {
        __syncthreads();
        if (tid < s) {
            float mv[KK]; int mi[KK];
            int ia = 0, ib = 0;
#pragma unroll
            for (int j = 0; j < KK; j++) {
                float va = sv[tid][ia],     vb = sv[tid + s][ib];
                int   xa = si[tid][ia],     xb = si[tid + s][ib];
                bool takeA = (va > vb) || (va == vb && xa < xb);
                if (takeA) { mv[j] = va; mi[j] = xa; ia++; }
                else       { mv[j] = vb; mi[j] = xb; ib++; }
            }
#pragma unroll
            for (int j = 0; j < KK; j++) { sv[tid][j] = mv[j]; si[tid][j] = mi[j]; }
        }
    }
    __syncthreads();
    if (tid < KK) g_fg_idx[b * FF + c * KK + tid] = si[0][tid];
}

// -------- prep: unique-point slots, flags, weights, reduction init --------
__global__ void k_prep(const int* __restrict__ click, const int* __restrict__ label,
                       const int* __restrict__ clsnum) {
    int b = blockIdx.x, tid = threadIdx.x;
    int cn = clsnum ? clsnum[0] : CC;
    __shared__ int w[TT];
    __shared__ int woff[8];
    __shared__ int sbase, sbg;
    for (int t = tid; t < TT; t += 256) w[t] = 0;
    unsigned encBig = fenc(BIGV), encNeg = fenc(-BIGV);
    for (int p = tid; p < PT; p += 256) {
        g_minff[b * PT + p] = encBig;
        g_maxfb[b * PT + p] = encNeg;
        g_minbb[b * PT + p] = encBig;
        g_maxbf[b * PT + p] = encNeg;
    }
    if (tid == 0) { sbase = 0; sbg = 0; }
    __syncthreads();
    for (int i = tid; i < FF; i += 256) {
        int c = i / KK;
        if (label[b * CC + c] == 1) atomicAdd(&w[g_fg_idx[b * FF + i]], 1);
    }
    __syncthreads();
    for (int chunk = 0; chunk < TT; chunk += 256) {
        int t = chunk + tid;
        int bg  = (click[b * TT + t] == cn) ? 1 : 0;
        int wt  = w[t];
        int sel = (bg || wt > 0) ? 1 : 0;
        unsigned ball = __ballot_sync(0xffffffffu, sel);
        unsigned ballbg = __ballot_sync(0xffffffffu, bg);
        int wi = tid >> 5, lane = tid & 31;
        if (lane == 0) { woff[wi] = __popc(ball); atomicAdd(&sbg, __popc(ballbg)); }
        __syncthreads();
        if (tid == 0) {
            int s = sbase;
            for (int i = 0; i < 8; i++) { int cc2 = woff[i]; woff[i] = s; s += cc2; }
            sbase = s;
        }
        __syncthreads();
        if (sel) {
            int pos = woff[wi] + __popc(ball & ((1u << lane) - 1u));
            g_slotmap[b * TT + t] = pos;
            g_sw[b * PT + pos] = wt;
            g_sfg[b * PT + pos] = (wt > 0) ? 1 : 0;
            g_sbg[b * PT + pos] = (unsigned char)bg;
        } else {
            g_slotmap[b * TT + t] = -1;
        }
        __syncthreads();
    }
    if (tid == 0) {
        int numpos = 0;
        for (int c = 0; c < CC; c++) numpos += (label[b * CC + c] == 1) ? 1 : 0;
        g_sumw[b]  = KK * numpos;
        g_bgcnt[b] = sbg;
        g_Nb[b]    = sbase;
        g_tiles[b] = (sbase + TS - 1) / TS;
    }
}

// -------- transpose-gather: 4 d-rows/block, 8 loads in flight, shared slotmap --------
__global__ void k_gatherT(const float* __restrict__ emb) {
    int b = blockIdx.y, tid = threadIdx.x;
    int d0 = blockIdx.x * 4;
    __shared__ int smap[TT];
#pragma unroll
    for (int i = 0; i < 8; i++) smap[tid + i * 256] = g_slotmap[b * TT + tid + i * 256];
    __syncthreads();

    const float4* src = (const float4*)(emb + ((size_t)b * DD + d0) * TT);
    float4 v[8];
#pragma unroll
    for (int dd = 0; dd < 4; dd++) {
#pragma unroll
        for (int it = 0; it < 2; it++)
            v[dd * 2 + it] = src[dd * (TT / 4) + tid + it * 256];
    }
    int sA[4], sB[4];
    {
        int t0 = tid * 4, t1 = (tid + 256) * 4;
#pragma unroll
        for (int j = 0; j < 4; j++) { sA[j] = smap[t0 + j]; sB[j] = smap[t1 + j]; }
    }
#pragma unroll
    for (int dd = 0; dd < 4; dd++) {
        float* dst = g_Et + ((size_t)b * DD + d0 + dd) * PT;
        float4 a = v[dd * 2], c = v[dd * 2 + 1];
        if (sA[0] >= 0) dst[sA[0]] = a.x;
        if (sA[1] >= 0) dst[sA[1]] = a.y;
        if (sA[2] >= 0) dst[sA[2]] = a.z;
        if (sA[3] >= 0) dst[sA[3]] = a.w;
        if (sB[0] >= 0) dst[sB[0]] = c.x;
        if (sB[1] >= 0) dst[sB[1]] = c.y;
        if (sB[2] >= 0) dst[sB[2]] = c.z;
        if (sB[3] >= 0) dst[sB[3]] = c.w;
    }
}

// -------- routing: per-row min/max over typed columns, atomic-merged --------
__device__ __forceinline__ void route_tile(const float acc[4][4], int b,
                                           int rowb, int colb, int Nb,
                                           int tx, int ty,
                                           const float* __restrict__ nrR,
                                           const float* __restrict__ nrC) {
    float nc[4]; int cfg[4], cbg[4];
#pragma unroll
    for (int j = 0; j < 4; j++) {
        int lc = 4 * tx + j;
        int c = colb + lc;
        bool cok = (c < Nb);
        nc[j]  = nrC[lc];
        cfg[j] = cok && g_sfg[b * PT + c];
        cbg[j] = cok && g_sbg[b * PT + c];
    }
#pragma unroll
    for (int i = 0; i < 4; i++) {
        int lr = 4 * ty + i;
        int ri = rowb + lr;
        float nr = nrR[lr];
        float vFF = BIGV, vBF = -BIGV, vFB = -BIGV, vBB = BIGV;
#pragma unroll
        for (int j = 0; j < 4; j++) {
            float cs = acc[i][j] / fmaxf(nr * nc[j], EPSV);
            if (cfg[j]) { vFF = fminf(vFF, cs); vBF = fmaxf(vBF, cs); }
            if (cbg[j]) { vFB = fmaxf(vFB, cs); vBB = fminf(vBB, cs); }
        }
#pragma unroll
        for (int m = 4; m > 0; m >>= 1) {
            vFF = fminf(vFF, __shfl_xor_sync(0xffffffffu, vFF, m));
            vBF = fmaxf(vBF, __shfl_xor_sync(0xffffffffu, vBF, m));
            vFB = fmaxf(vFB, __shfl_xor_sync(0xffffffffu, vFB, m));
            vBB = fminf(vBB, __shfl_xor_sync(0xffffffffu, vBB, m));
        }
        if (tx == 0 && ri < Nb) {
            if (g_sfg[b * PT + ri]) {
                atomicMin(&g_minff[b * PT + ri], fenc(vFF));
                atomicMax(&g_maxfb[b * PT + ri], fenc(vFB));
            }
            if (g_sbg[b * PT + ri]) {
                atomicMax(&g_maxbf[b * PT + ri], fenc(vBF));
                atomicMin(&g_minbb[b * PT + ri], fenc(vBB));
            }
        }
    }
}

// -------- fused symmetric tiled similarity: k-split across 4 groups of 64 --------
__global__ void __launch_bounds__(256) k_sim() {
    __shared__ float As[4][DKC][TS];     // 16 KB; reused as partial-acc buffer after mainloop
    __shared__ float Bs[4][DKC][TS];     // 16 KB
    __shared__ float sqAs[4][8][32];     // 4 KB
    __shared__ float sqBs[4][8][32];     // 4 KB
    __shared__ float nrmA[TS], nrmB[TS];
    __shared__ int   s_off[BN + 1];

    int tid = threadIdx.x;
    int g = tid >> 6, lin = tid & 63;
    int tx = lin & 7, ty = lin >> 3;
    int slice = lin >> 3;                // 0..7, staging dk slice
    int pq = (lin & 7) * 4;              // staging point group

    if (tid == 0) {
        int off = 0;
        for (int b = 0; b < BN; b++) { s_off[b] = off; int t = g_tiles[b]; off += t * (t + 1) / 2; }
        s_off[BN] = off;
    }
    __syncthreads();
    int total = s_off[BN];

    for (int item = blockIdx.x; item < total; item += gridDim.x) {
        int b = 0;
        while (b < BN - 1 && item >= s_off[b + 1]) b++;
        int local = item - s_off[b];
        int tiles = g_tiles[b];
        int rt = 0, rem = local;
        while (rem >= tiles - rt) { rem -= tiles - rt; rt++; }
        int ct = rt + rem;
        int Nb = g_Nb[b];
        int rowb = rt * TS, colb = ct * TS;

        float acc[4][4];
#pragma unroll
        for (int i = 0; i < 4; i++)
#pragma unroll
            for (int j = 0; j < 4; j++) acc[i][j] = 0.f;
        float4 sqa = {0.f, 0.f, 0.f, 0.f}, sqb = {0.f, 0.f, 0.f, 0.f};

        const float* Eb = g_Et + (size_t)b * DD * PT;
        // group g covers d in [128g, 128g+128), 4 sub-chunks of 32
#pragma unroll 1
        for (int s = 0; s < 4; s++) {
            int d0 = g * 128 + s * DKC;
#pragma unroll
            for (int i = 0; i < 4; i++) {
                int dk = i * 8 + slice;
                const float* rsrc = Eb + (size_t)(d0 + dk) * PT;
                float4 r = *(const float4*)(rsrc + rowb + pq);
                float4 c = *(const float4*)(rsrc + colb + pq);
                *(float4*)&As[g][dk][pq] = r;
                *(float4*)&Bs[g][dk][pq] = c;
                sqa.x += r.x * r.x; sqa.y += r.y * r.y; sqa.z += r.z * r.z; sqa.w += r.w * r.w;
                sqb.x += c.x * c.x; sqb.y += c.y * c.y; sqb.z += c.z * c.z; sqb.w += c.w * c.w;
            }
            asm volatile("bar.sync %0, 64;" :: "r"(g + 1) : "memory");
#pragma unroll
            for (int dk = 0; dk < DKC; dk++) {
                float4 a = *(const float4*)&As[g][dk][ty * 4];
                float4 c = *(const float4*)&Bs[g][dk][tx * 4];
                acc[0][0] += a.x * c.x; acc[0][1] += a.x * c.y; acc[0][2] += a.x * c.z; acc[0][3] += a.x * c.w;
                acc[1][0] += a.y * c.x; acc[1][1] += a.y * c.y; acc[1][2] += a.y * c.z; acc[1][3] += a.y * c.w;
                acc[2][0] += a.z * c.x; acc[2][1] += a.z * c.y; acc[2][2] += a.z * c.z; acc[2][3] += a.z * c.w;
                acc[3][0] += a.w * c.x; acc[3][1] += a.w * c.y; acc[3][2] += a.w * c.z; acc[3][3] += a.w * c.w;
            }
            asm volatile("bar.sync %0, 64;" :: "r"(g + 1) : "memory");
        }

        // store sq partials and acc partials (acc into group's own As slice: safe)
        *(float4*)&sqAs[g][slice][pq] = sqa;
        *(float4*)&sqBs[g][slice][pq] = sqb;
        float* part = &As[0][0][0];          // [g][lin][16] layout, 4*64*16 = 4096 floats
        {
            float* mp = part + (g * 64 + lin) * 16;
#pragma unroll
            for (int i = 0; i < 4; i++)
#pragma unroll
                for (int j = 0; j < 4; j++) mp[i * 4 + j] = acc[i][j];
        }
        __syncthreads();

        // norms: fixed combine order (g asc, slice asc) -> identical for a point in every tile
        if (tid < 32) {
            float ssum = 0.f;
#pragma unroll
            for (int gg = 0; gg < 4; gg++)
#pragma unroll
                for (int k = 0; k < 8; k++) ssum += sqAs[gg][k][tid];
            nrmA[tid] = sqrtf(ssum);
        } else if (tid < 64) {
            int p = tid - 32;
            float ssum = 0.f;
#pragma unroll
            for (int gg = 0; gg < 4; gg++)
#pragma unroll
                for (int k = 0; k < 8; k++) ssum += sqBs[gg][k][p];
            nrmB[p] = sqrtf(ssum);
        }
        __syncthreads();

        if (g == 0) {
            float a2[4][4];
#pragma unroll
            for (int i = 0; i < 4; i++)
#pragma unroll
                for (int j = 0; j < 4; j++) {
                    int o = lin * 16 + i * 4 + j;
                    a2[i][j] = ((part[o] + part[1024 + o]) + (part[2048 + o] + part[3072 + o]));
                }
            route_tile(a2, b, rowb, colb, Nb, tx, ty, nrmA, nrmB);
        } else if (g == 1 && rt != ct) {
            int lin0 = (tx << 3) | ty;   // thread holding the transposed micro-tile
            float a2[4][4];
#pragma unroll
            for (int i = 0; i < 4; i++)
#pragma unroll
                for (int j = 0; j < 4; j++) {
                    int o = lin0 * 16 + j * 4 + i;
                    a2[i][j] = ((part[o] + part[1024 + o]) + (part[2048 + o] + part[3072 + o]));
                }
            route_tile(a2, b, colb, rowb, Nb, tx, ty, nrmB, nrmA);
        }
        __syncthreads();
    }
}

// -------- per-batch weighted means + fused final (last-block ticket) --------
__global__ void k_batch(float* __restrict__ out) {
    int b = blockIdx.x, tid = threadIdx.x;
    int Nb = g_Nb[b];
    float sff = 0.f, sfb = 0.f, sbb = 0.f, sbf = 0.f;
    for (int p = tid; p < Nb; p += 256) {
        if (g_sfg[b * PT + p]) {
            float wv = (float)g_sw[b * PT + p];
            sff += wv * fmaxf(THSIM - fdec(g_minff[b * PT + p]), 0.f);
            sfb += wv * fmaxf(fdec(g_maxfb[b * PT + p]) - THDIF, 0.f);
        }
        if (g_sbg[b * PT + p]) {
            sbb += fmaxf(THSIM - fdec(g_minbb[b * PT + p]), 0.f);
            sbf += fmaxf(fdec(g_maxbf[b * PT + p]) - THDIF, 0.f);
        }
    }
    __shared__ float r1[256], r2[256], r3[256], r4[256];
    __shared__ int s_last;
    r1[tid] = sff; r2[tid] = sfb; r3[tid] = sbb; r4[tid] = sbf;
    __syncthreads();
    for (int s = 128; s > 0; s >>= 1) {
        if (tid < s) {
            r1[tid] += r1[tid + s]; r2[tid] += r2[tid + s];
            r3[tid] += r3[tid + s]; r4[tid] += r4[tid + s];
        }
        __syncthreads();
    }
    if (tid == 0) {
        int cnt = g_bgcnt[b];
        float denf = fmaxf((float)g_sumw[b], 1.f);
        float denb = fmaxf((float)cnt, 1.f);
        float loss = r1[0] / denf + r2[0] / denf + r3[0] / denb + r4[0] / denb;
        g_perbatch[b] = (cnt > 0) ? loss : 0.f;
        __threadfence();
        int old = atomicAdd(&g_ticket, 1);
        s_last = (old == BN - 1) ? 1 : 0;
    }
    __syncthreads();
    if (s_last && tid == 0) {
        volatile float* pb = g_perbatch;
        float s = 0.f; int c = 0;
        for (int bb = 0; bb < BN; bb++) { s += pb[bb]; if (g_bgcnt[bb] > 0) c++; }
        out[0] = s / fmaxf((float)c, 1.f);
        g_ticket = 0;   // reset for next graph replay
    }
}

extern "C" void kernel_launch(void* const* d_in, const int* in_sizes, int n_in,
                              void* d_out, int out_size) {
    const float* emb    = (const float*)d_in[0];
    const float* cas    = (const float*)d_in[1];
    const int*   click  = (const int*)d_in[2];
    const int*   label  = (const int*)d_in[3];
    const int*   clsnum = (n_in >= 5) ? (const int*)d_in[4] : nullptr;

    k_topk   <<<dim3(CC, BN), 256>>>(cas);
    k_prep   <<<BN, 256>>>(click, label, clsnum);
    k_gatherT<<<dim3(DD / 4, BN), 256>>>(emb);
    k_sim    <<<SIM_BLOCKS, 256>>>();
    k_batch  <<<BN, 256>>>((float*)d_out);
}